// round 8
// baseline (speedup 1.0000x reference)
#include <cuda_runtime.h>
#include <math_constants.h>

#define D_MODEL 1024
#define N_HEADS 16
#define D_HEAD  64
#define WINDOW  256
#define SEQ     2048
#define BATCH   2
#define M_ROWS  (BATCH * SEQ)   // 4096
#define QKV_LD  (3 * D_MODEL)   // 3072

// Scratch (allocation-free rule: __device__ globals)
__device__ float g_qkv[(size_t)M_ROWS * QKV_LD];     // [4096][3072] fp32
__device__ float g_att[(size_t)M_ROWS * D_MODEL];    // [4096][1024] tf32-rounded
__device__ float g_xc[(size_t)M_ROWS * D_MODEL];     // x, tf32-rounded
__device__ float g_wqkvc[(size_t)D_MODEL * QKV_LD];  // W_qkv, tf32-rounded
__device__ float g_woutc[(size_t)D_MODEL * D_MODEL]; // W_out, tf32-rounded

// ---------------------------------------------------------------------------
// helpers (compute_103-safe PTX only: sm_80-era instructions)
// ---------------------------------------------------------------------------
__device__ __forceinline__ float to_tf32(float x) {
    unsigned u;
    asm("cvt.rna.tf32.f32 %0, %1;" : "=r"(u) : "f"(x));
    return __uint_as_float(u);
}
__device__ __forceinline__ float4 cvt4(float4 v) {
    v.x = to_tf32(v.x); v.y = to_tf32(v.y); v.z = to_tf32(v.z); v.w = to_tf32(v.w);
    return v;
}
__device__ __forceinline__ unsigned smem_u32(const void* p) {
    unsigned r;
    asm("{ .reg .u64 t; cvta.to.shared.u64 t, %1; cvt.u32.u64 %0, t; }"
        : "=r"(r) : "l"(p));
    return r;
}
__device__ __forceinline__ void mma_tf32(float* c,
                                         unsigned a0, unsigned a1, unsigned a2, unsigned a3,
                                         unsigned b0, unsigned b1) {
    asm volatile(
        "mma.sync.aligned.m16n8k8.row.col.f32.tf32.tf32.f32 "
        "{%0,%1,%2,%3}, {%4,%5,%6,%7}, {%8,%9}, {%0,%1,%2,%3};\n"
        : "+f"(c[0]), "+f"(c[1]), "+f"(c[2]), "+f"(c[3])
        : "r"(a0), "r"(a1), "r"(a2), "r"(a3), "r"(b0), "r"(b1));
}
__device__ __forceinline__ void cp16(unsigned dst, const float* src) {
    asm volatile("cp.async.cg.shared.global [%0], [%1], 16;\n" :: "r"(dst), "l"(src));
}
#define CP_COMMIT() asm volatile("cp.async.commit_group;\n" ::: "memory")
#define CP_WAIT(n)  asm volatile("cp.async.wait_group %0;\n" :: "n"(n) : "memory")

// ---------------------------------------------------------------------------
// elementwise tf32 rounding (one-shot; hoists cvt off the GEMM path)
// ---------------------------------------------------------------------------
__global__ void cvt_tf32_vec(const float4* __restrict__ in, float4* __restrict__ out,
                             int n4) {
    int i = blockIdx.x * blockDim.x + threadIdx.x;
    if (i < n4) out[i] = cvt4(in[i]);
}

// ---------------------------------------------------------------------------
// Pipelined tf32 GEMM: C[M,N] = A[M,K] @ B[K,N] + bias[N]
// A, B must be pre-rounded to tf32. CTA 128x128, BK=32, 2-stage cp.async,
// 4 warps of 64x64, mma.sync.m16n8k8. M%128==0, N%128==0, K%32==0.
// ---------------------------------------------------------------------------
#define A_ROW 36                    // floats per A smem row (pad: 4g+tg bijective)
#define B_ROW 136                   // floats per B smem row (pad: 8tg+g bijective)
#define A_OFF_F 0
#define B_OFF_F (128 * A_ROW)                       // 4608 floats
#define STAGE_F (128 * A_ROW + 32 * B_ROW)          // 8960 floats = 35840 B
#define GEMM_SMEM (2 * STAGE_F * 4)                 // 71680 B

__device__ __forceinline__ void load_chunk(unsigned sbase, int stage,
                                           const float* __restrict__ A,
                                           const float* __restrict__ B,
                                           int bm, int bn, int K, int N, int kb,
                                           int tid) {
    const unsigned sa = sbase + (unsigned)stage * (STAGE_F * 4);
    #pragma unroll
    for (int p = 0; p < 8; p++) {               // A: 128 rows x 8 float4
        int idx = tid + p * 128;
        int r = idx >> 3, q = idx & 7;
        cp16(sa + A_OFF_F * 4 + (unsigned)r * (A_ROW * 4) + q * 16,
             A + (size_t)(bm + r) * K + kb + q * 4);
    }
    #pragma unroll
    for (int p = 0; p < 8; p++) {               // B: 32 rows x 32 float4
        int idx = tid + p * 128;
        int r = idx >> 5, q = idx & 31;
        cp16(sa + B_OFF_F * 4 + (unsigned)r * (B_ROW * 4) + q * 16,
             B + (size_t)(kb + r) * N + bn + q * 4);
    }
    CP_COMMIT();
}

__global__ __launch_bounds__(128)
void gemm_tf32p(const float* __restrict__ A, const float* __restrict__ B,
                const float* __restrict__ bias, float* __restrict__ C,
                int M, int N, int K) {
    extern __shared__ float smf[];
    const unsigned sbase = smem_u32(smf);
    const int tid = threadIdx.x, lane = tid & 31, wid = tid >> 5;
    const int g = lane >> 2, tg = lane & 3;
    const int wm = (wid & 1) * 64, wn = (wid >> 1) * 64;
    const int bm = blockIdx.y * 128, bn = blockIdx.x * 128;

    float acc[4][8][4] = {};

    load_chunk(sbase, 0, A, B, bm, bn, K, N, 0, tid);

    const int NC = K / 32;
    for (int c = 0; c < NC; c++) {
        if (c + 1 < NC) {
            load_chunk(sbase, (c + 1) & 1, A, B, bm, bn, K, N, (c + 1) * 32, tid);
            CP_WAIT(1);                          // chunk c resident, c+1 in flight
        } else {
            CP_WAIT(0);
        }
        __syncthreads();

        const int sb = (c & 1) * STAGE_F;
        #pragma unroll
        for (int ks = 0; ks < 4; ks++) {
            const int k8 = ks * 8;
            unsigned a[4][4];
            #pragma unroll
            for (int mt = 0; mt < 4; mt++) {
                int r = wm + mt * 16 + g;
                a[mt][0] = __float_as_uint(smf[sb + r * A_ROW + k8 + tg]);
                a[mt][1] = __float_as_uint(smf[sb + (r + 8) * A_ROW + k8 + tg]);
                a[mt][2] = __float_as_uint(smf[sb + r * A_ROW + k8 + tg + 4]);
                a[mt][3] = __float_as_uint(smf[sb + (r + 8) * A_ROW + k8 + tg + 4]);
            }
            unsigned b0[8], b1[8];
            #pragma unroll
            for (int nt = 0; nt < 8; nt++) {
                int cc = wn + nt * 8 + g;
                b0[nt] = __float_as_uint(smf[sb + B_OFF_F + (k8 + tg) * B_ROW + cc]);
                b1[nt] = __float_as_uint(smf[sb + B_OFF_F + (k8 + tg + 4) * B_ROW + cc]);
            }
            #pragma unroll
            for (int mt = 0; mt < 4; mt++)
                #pragma unroll
                for (int nt = 0; nt < 8; nt++)
                    mma_tf32(acc[mt][nt], a[mt][0], a[mt][1], a[mt][2], a[mt][3],
                             b0[nt], b1[nt]);
        }
        __syncthreads();
    }

    // epilogue: c0,c1 -> (row, col..col+1); c2,c3 -> (row+8, ...)
    #pragma unroll
    for (int mt = 0; mt < 4; mt++) {
        #pragma unroll
        for (int nt = 0; nt < 8; nt++) {
            int r0 = bm + wm + mt * 16 + g;
            int c0 = bn + wn + nt * 8 + 2 * tg;
            float2 bv = *(const float2*)(bias + c0);
            float2 o0 = make_float2(acc[mt][nt][0] + bv.x, acc[mt][nt][1] + bv.y);
            float2 o1 = make_float2(acc[mt][nt][2] + bv.x, acc[mt][nt][3] + bv.y);
            *(float2*)(C + (size_t)r0 * N + c0)       = o0;
            *(float2*)(C + (size_t)(r0 + 8) * N + c0) = o1;
        }
    }
}

// ---------------------------------------------------------------------------
// Windowed attention (fp32 FFMA, at roofline). Anti-causal window [i, i+255].
// Output written tf32-rounded (feeds the out-proj GEMM directly).
// ---------------------------------------------------------------------------
#define SMPAD 68
#define ATTN_SMEM ((4 * 64 * SMPAD + 3 * 64) * 4)

__global__ __launch_bounds__(256)
void attn_win(const float* __restrict__ qkv, float* __restrict__ out) {
    extern __shared__ float sm[];
    float* Qt   = sm;                  // [d][i]  64x68
    float* Kt   = Qt + 64 * SMPAD;     // [d][j]
    float* Vs   = Kt + 64 * SMPAD;     // [j][d]
    float* Pt   = Vs + 64 * SMPAD;     // [j][i]
    float* mrow = Pt + 64 * SMPAD;
    float* lrow = mrow + 64;
    float* frow = lrow + 64;

    const int tid = threadIdx.x;
    const int tx  = tid & 15;
    const int ty  = tid >> 4;
    const int b   = blockIdx.z, h = blockIdx.y;
    const int qs  = blockIdx.x * 64;

    const int rr = tid >> 4;
    const int d4 = (tid & 15) << 2;

    const float* Qb = qkv + (size_t)(b * SEQ + qs) * QKV_LD + h * D_HEAD;
    #pragma unroll
    for (int p = 0; p < 4; p++) {
        int i = rr + p * 16;
        float4 v = *(const float4*)(Qb + (size_t)i * QKV_LD + d4);
        Qt[(d4 + 0) * SMPAD + i] = v.x;
        Qt[(d4 + 1) * SMPAD + i] = v.y;
        Qt[(d4 + 2) * SMPAD + i] = v.z;
        Qt[(d4 + 3) * SMPAD + i] = v.w;
    }
    if (tid < 64) { mrow[tid] = -CUDART_INF_F; lrow[tid] = 0.f; }

    float o[4][4];
    #pragma unroll
    for (int r = 0; r < 4; r++)
        #pragma unroll
        for (int c = 0; c < 4; c++) o[r][c] = 0.f;

    const float* Kbase = qkv + (size_t)(b * SEQ) * QKV_LD + D_MODEL + h * D_HEAD;
    const float* Vbase = Kbase + D_MODEL;

    for (int ch = 0; ch < 5; ch++) {
        __syncthreads();
        const int j0 = qs + ch * 64;

        #pragma unroll
        for (int p = 0; p < 4; p++) {
            int jj = rr + p * 16;
            int jr = min(j0 + jj, SEQ - 1);
            float4 kv = *(const float4*)(Kbase + (size_t)jr * QKV_LD + d4);
            Kt[(d4 + 0) * SMPAD + jj] = kv.x;
            Kt[(d4 + 1) * SMPAD + jj] = kv.y;
            Kt[(d4 + 2) * SMPAD + jj] = kv.z;
            Kt[(d4 + 3) * SMPAD + jj] = kv.w;
            float4 vv = *(const float4*)(Vbase + (size_t)jr * QKV_LD + d4);
            *(float4*)(Vs + jj * SMPAD + d4) = vv;
        }
        __syncthreads();

        float s[4][4];
        #pragma unroll
        for (int r = 0; r < 4; r++)
            #pragma unroll
            for (int c = 0; c < 4; c++) s[r][c] = 0.f;
        #pragma unroll
        for (int d = 0; d < 64; d++) {
            float4 q4 = *(const float4*)(Qt + d * SMPAD + 4 * ty);
            float4 k4 = *(const float4*)(Kt + d * SMPAD + 4 * tx);
            s[0][0] += q4.x * k4.x; s[0][1] += q4.x * k4.y; s[0][2] += q4.x * k4.z; s[0][3] += q4.x * k4.w;
            s[1][0] += q4.y * k4.x; s[1][1] += q4.y * k4.y; s[1][2] += q4.y * k4.z; s[1][3] += q4.y * k4.w;
            s[2][0] += q4.z * k4.x; s[2][1] += q4.z * k4.y; s[2][2] += q4.z * k4.z; s[2][3] += q4.z * k4.w;
            s[3][0] += q4.w * k4.x; s[3][1] += q4.w * k4.y; s[3][2] += q4.w * k4.z; s[3][3] += q4.w * k4.w;
        }
        #pragma unroll
        for (int r = 0; r < 4; r++) {
            #pragma unroll
            for (int c = 0; c < 4; c++) {
                int qi = 4 * ty + r, jl = 4 * tx + c;
                int dj = ch * 64 + jl - qi;
                bool keep = (dj >= 0) && (dj < WINDOW) && (j0 + jl < SEQ);
                Pt[jl * SMPAD + qi] = keep ? s[r][c] * 0.125f : -CUDART_INF_F;
            }
        }
        __syncthreads();

        if (tid < 64) {
            float m = mrow[tid];
            float mc = -CUDART_INF_F;
            #pragma unroll
            for (int jl = 0; jl < 64; jl++) mc = fmaxf(mc, Pt[jl * SMPAD + tid]);
            float mn = fmaxf(m, mc);
            float f  = __expf(m - mn);
            float ssum = 0.f;
            #pragma unroll
            for (int jl = 0; jl < 64; jl++) {
                float p = __expf(Pt[jl * SMPAD + tid] - mn);
                ssum += p;
                Pt[jl * SMPAD + tid] = p;
            }
            lrow[tid] = lrow[tid] * f + ssum;
            mrow[tid] = mn;
            frow[tid] = f;
        }
        __syncthreads();

        float fr0 = frow[4 * ty + 0], fr1 = frow[4 * ty + 1];
        float fr2 = frow[4 * ty + 2], fr3 = frow[4 * ty + 3];
        #pragma unroll
        for (int c = 0; c < 4; c++) {
            o[0][c] *= fr0; o[1][c] *= fr1; o[2][c] *= fr2; o[3][c] *= fr3;
        }
        #pragma unroll
        for (int jl = 0; jl < 64; jl++) {
            float4 p4 = *(const float4*)(Pt + jl * SMPAD + 4 * ty);
            float4 v4 = *(const float4*)(Vs + jl * SMPAD + 4 * tx);
            o[0][0] += p4.x * v4.x; o[0][1] += p4.x * v4.y; o[0][2] += p4.x * v4.z; o[0][3] += p4.x * v4.w;
            o[1][0] += p4.y * v4.x; o[1][1] += p4.y * v4.y; o[1][2] += p4.y * v4.z; o[1][3] += p4.y * v4.w;
            o[2][0] += p4.z * v4.x; o[2][1] += p4.z * v4.y; o[2][2] += p4.z * v4.z; o[2][3] += p4.z * v4.w;
            o[3][0] += p4.w * v4.x; o[3][1] += p4.w * v4.y; o[3][2] += p4.w * v4.z; o[3][3] += p4.w * v4.w;
        }
    }

    #pragma unroll
    for (int r = 0; r < 4; r++) {
        int qi = 4 * ty + r;
        float inv = 1.f / lrow[qi];
        float4 res = make_float4(to_tf32(o[r][0] * inv), to_tf32(o[r][1] * inv),
                                 to_tf32(o[r][2] * inv), to_tf32(o[r][3] * inv));
        *(float4*)(out + (size_t)(b * SEQ + qs + qi) * D_MODEL + h * D_HEAD + 4 * tx) = res;
    }
}

// ---------------------------------------------------------------------------
extern "C" void kernel_launch(void* const* d_in, const int* in_sizes, int n_in,
                              void* d_out, int out_size) {
    const float* x    = (const float*)d_in[0];   // [2,2048,1024]
    const float* Wqkv = (const float*)d_in[1];   // [1024,3072]
    const float* bqkv = (const float*)d_in[2];   // [3072]
    const float* Wout = (const float*)d_in[3];   // [1024,1024]
    const float* bout = (const float*)d_in[4];   // [1024]
    float* out = (float*)d_out;                  // [2,2048,1024] f32

    float *qkv, *att, *xc, *wqkvc, *woutc;
    cudaGetSymbolAddress((void**)&qkv,   g_qkv);
    cudaGetSymbolAddress((void**)&att,   g_att);
    cudaGetSymbolAddress((void**)&xc,    g_xc);
    cudaGetSymbolAddress((void**)&wqkvc, g_wqkvc);
    cudaGetSymbolAddress((void**)&woutc, g_woutc);

    cudaFuncSetAttribute(attn_win, cudaFuncAttributeMaxDynamicSharedMemorySize,
                         ATTN_SMEM);
    cudaFuncSetAttribute(gemm_tf32p, cudaFuncAttributeMaxDynamicSharedMemorySize,
                         GEMM_SMEM);

    // 0) one-shot tf32 rounding of GEMM inputs
    {
        int n4x = M_ROWS * D_MODEL / 4;
        cvt_tf32_vec<<<(n4x + 255) / 256, 256>>>((const float4*)x, (float4*)xc, n4x);
        int n4q = D_MODEL * QKV_LD / 4;
        cvt_tf32_vec<<<(n4q + 255) / 256, 256>>>((const float4*)Wqkv, (float4*)wqkvc, n4q);
        int n4o = D_MODEL * D_MODEL / 4;
        cvt_tf32_vec<<<(n4o + 255) / 256, 256>>>((const float4*)Wout, (float4*)woutc, n4o);
    }

    // 1) QKV projection: [4096,1024] @ [1024,3072] + b
    gemm_tf32p<<<dim3(QKV_LD / 128, M_ROWS / 128), 128, GEMM_SMEM>>>(
        xc, wqkvc, bqkv, qkv, M_ROWS, QKV_LD, D_MODEL);

    // 2) windowed attention (emits tf32-rounded output)
    attn_win<<<dim3(SEQ / 64, N_HEADS, BATCH), 256, ATTN_SMEM>>>(qkv, att);

    // 3) output projection: [4096,1024] @ [1024,1024] + b -> d_out
    gemm_tf32p<<<dim3(D_MODEL / 128, M_ROWS / 128), 128, GEMM_SMEM>>>(
        att, woutc, bout, out, M_ROWS, D_MODEL, D_MODEL);
}

// round 9
// speedup vs baseline: 1.5490x; 1.5490x over previous
#include <cuda_runtime.h>
#include <math_constants.h>

#define D_MODEL 1024
#define N_HEADS 16
#define D_HEAD  64
#define WINDOW  256
#define SEQ     2048
#define BATCH   2
#define M_ROWS  (BATCH * SEQ)   // 4096
#define QKV_LD  (3 * D_MODEL)   // 3072

// Scratch (allocation-free rule: __device__ globals)
__device__ float g_qkv[(size_t)M_ROWS * QKV_LD];     // [4096][3072] fp32
__device__ float g_att[(size_t)M_ROWS * D_MODEL];    // [4096][1024] tf32-rounded
__device__ float g_xc[(size_t)M_ROWS * D_MODEL];     // x, tf32-rounded
__device__ float g_wqkvc[(size_t)D_MODEL * QKV_LD];  // W_qkv, tf32-rounded
__device__ float g_woutc[(size_t)D_MODEL * D_MODEL]; // W_out, tf32-rounded

// ---------------------------------------------------------------------------
// helpers (compute_103-safe PTX only: sm_80-era instructions)
// ---------------------------------------------------------------------------
__device__ __forceinline__ float to_tf32(float x) {
    unsigned u;
    asm("cvt.rna.tf32.f32 %0, %1;" : "=r"(u) : "f"(x));
    return __uint_as_float(u);
}
__device__ __forceinline__ float4 cvt4(float4 v) {
    v.x = to_tf32(v.x); v.y = to_tf32(v.y); v.z = to_tf32(v.z); v.w = to_tf32(v.w);
    return v;
}
__device__ __forceinline__ unsigned smem_u32(const void* p) {
    unsigned r;
    asm("{ .reg .u64 t; cvta.to.shared.u64 t, %1; cvt.u32.u64 %0, t; }"
        : "=r"(r) : "l"(p));
    return r;
}
__device__ __forceinline__ void mma_tf32(float* c,
                                         unsigned a0, unsigned a1, unsigned a2, unsigned a3,
                                         unsigned b0, unsigned b1) {
    asm volatile(
        "mma.sync.aligned.m16n8k8.row.col.f32.tf32.tf32.f32 "
        "{%0,%1,%2,%3}, {%4,%5,%6,%7}, {%8,%9}, {%0,%1,%2,%3};\n"
        : "+f"(c[0]), "+f"(c[1]), "+f"(c[2]), "+f"(c[3])
        : "r"(a0), "r"(a1), "r"(a2), "r"(a3), "r"(b0), "r"(b1));
}
__device__ __forceinline__ void cp16(unsigned dst, const float* src) {
    asm volatile("cp.async.cg.shared.global [%0], [%1], 16;\n" :: "r"(dst), "l"(src));
}
#define CP_COMMIT() asm volatile("cp.async.commit_group;\n" ::: "memory")
#define CP_WAIT(n)  asm volatile("cp.async.wait_group %0;\n" :: "n"(n) : "memory")

// ---------------------------------------------------------------------------
// elementwise tf32 rounding (one-shot; hoists cvt off the GEMM path)
// ---------------------------------------------------------------------------
__global__ void cvt_tf32_vec(const float4* __restrict__ in, float4* __restrict__ out,
                             int n4) {
    int i = blockIdx.x * blockDim.x + threadIdx.x;
    if (i < n4) out[i] = cvt4(in[i]);
}

// ---------------------------------------------------------------------------
// Pipelined tf32 GEMM: C[M,N] = A[M,K] @ B[K,N] + bias[N]
// A, B pre-rounded to tf32. CTA 128x128, BK=32, 3-stage cp.async ring,
// ONE __syncthreads per chunk, 8 warps of 32x64, mma.sync.m16n8k8.
// M%128==0, N%128==0, K%32==0. 2 CTAs/SM (smem 105KB, <=128 regs).
// ---------------------------------------------------------------------------
#define A_ROW 36                           // floats/row (36 == 4 mod 32 -> frag LDS conflict-free)
#define B_ROW 136                          // floats/row (136 == 8 mod 32)
#define A_BYTES (128 * A_ROW * 4)          // 18432
#define B_OFF_B A_BYTES
#define B_OFF_F (128 * A_ROW)              // float index of B region
#define STAGE_B (A_BYTES + 32 * B_ROW * 4) // 35840 B
#define STAGE_F (STAGE_B / 4)              // 8960 floats
#define NSTAGE 3
#define GEMM_SMEM (NSTAGE * STAGE_B)       // 107520 B

__device__ __forceinline__ void load_chunk(unsigned sbase, int stage,
                                           const float* __restrict__ A,
                                           const float* __restrict__ B,
                                           int bm, int bn, int K, int N, int kb,
                                           int tid) {
    const unsigned sa = sbase + (unsigned)stage * STAGE_B;
    #pragma unroll
    for (int p = 0; p < 4; p++) {               // A: 128 rows x 8 float4
        int idx = tid + p * 256;
        int r = idx >> 3, q = idx & 7;
        cp16(sa + (unsigned)r * (A_ROW * 4) + q * 16,
             A + (size_t)(bm + r) * K + kb + q * 4);
    }
    #pragma unroll
    for (int p = 0; p < 4; p++) {               // B: 32 rows x 32 float4
        int idx = tid + p * 256;
        int r = idx >> 5, q = idx & 31;
        cp16(sa + B_OFF_B + (unsigned)r * (B_ROW * 4) + q * 16,
             B + (size_t)(kb + r) * N + bn + q * 4);
    }
}

__global__ __launch_bounds__(256, 2)
void gemm_tf32p(const float* __restrict__ A, const float* __restrict__ B,
                const float* __restrict__ bias, float* __restrict__ C,
                int M, int N, int K) {
    extern __shared__ float smf[];
    const unsigned sbase = smem_u32(smf);
    const int tid = threadIdx.x, lane = tid & 31, wid = tid >> 5;
    const int g = lane >> 2, tg = lane & 3;
    const int wm = (wid & 3) * 32, wn = (wid >> 2) * 64;   // 4m x 2n warp grid
    const int bm = blockIdx.y * 128, bn = blockIdx.x * 128;
    const int NC = K / 32;

    float acc[2][8][4] = {};

    // prologue: stages 0 and 1 in flight
    load_chunk(sbase, 0, A, B, bm, bn, K, N, 0, tid);
    CP_COMMIT();
    load_chunk(sbase, 1, A, B, bm, bn, K, N, 32, tid);
    CP_COMMIT();

    int stage = 0;
    for (int c = 0; c < NC; c++) {
        CP_WAIT(1);                 // chunk c resident (c+1 may still fly)
        __syncthreads();            // all warps done with stage (c-1)%3 == (c+2)%3

        if (c + 2 < NC)
            load_chunk(sbase, (stage + 2) % NSTAGE, A, B, bm, bn, K, N,
                       (c + 2) * 32, tid);
        CP_COMMIT();                // uniform group counting (may be empty)

        const int sb = stage * STAGE_F;
        #pragma unroll
        for (int ks = 0; ks < 4; ks++) {
            const int k8 = ks * 8;
            unsigned a[2][4];
            #pragma unroll
            for (int mt = 0; mt < 2; mt++) {
                int r = wm + mt * 16 + g;
                a[mt][0] = __float_as_uint(smf[sb + r * A_ROW + k8 + tg]);
                a[mt][1] = __float_as_uint(smf[sb + (r + 8) * A_ROW + k8 + tg]);
                a[mt][2] = __float_as_uint(smf[sb + r * A_ROW + k8 + tg + 4]);
                a[mt][3] = __float_as_uint(smf[sb + (r + 8) * A_ROW + k8 + tg + 4]);
            }
            unsigned b0[8], b1[8];
            #pragma unroll
            for (int nt = 0; nt < 8; nt++) {
                int cc = wn + nt * 8 + g;
                b0[nt] = __float_as_uint(smf[sb + B_OFF_F + (k8 + tg) * B_ROW + cc]);
                b1[nt] = __float_as_uint(smf[sb + B_OFF_F + (k8 + tg + 4) * B_ROW + cc]);
            }
            #pragma unroll
            for (int mt = 0; mt < 2; mt++)
                #pragma unroll
                for (int nt = 0; nt < 8; nt++)
                    mma_tf32(acc[mt][nt], a[mt][0], a[mt][1], a[mt][2], a[mt][3],
                             b0[nt], b1[nt]);
        }
        stage = (stage + 1 == NSTAGE) ? 0 : stage + 1;
    }

    // epilogue: c0,c1 -> (row, col..col+1); c2,c3 -> (row+8, ...)
    #pragma unroll
    for (int mt = 0; mt < 2; mt++) {
        #pragma unroll
        for (int nt = 0; nt < 8; nt++) {
            int r0 = bm + wm + mt * 16 + g;
            int c0 = bn + wn + nt * 8 + 2 * tg;
            float2 bv = *(const float2*)(bias + c0);
            float2 o0 = make_float2(acc[mt][nt][0] + bv.x, acc[mt][nt][1] + bv.y);
            float2 o1 = make_float2(acc[mt][nt][2] + bv.x, acc[mt][nt][3] + bv.y);
            *(float2*)(C + (size_t)r0 * N + c0)       = o0;
            *(float2*)(C + (size_t)(r0 + 8) * N + c0) = o1;
        }
    }
}

// ---------------------------------------------------------------------------
// Windowed attention (fp32 FFMA). Anti-causal window [i, i+255].
// Output written tf32-rounded (feeds the out-proj GEMM directly).
// ---------------------------------------------------------------------------
#define SMPAD 68
#define ATTN_SMEM ((4 * 64 * SMPAD + 3 * 64) * 4)

__global__ __launch_bounds__(256)
void attn_win(const float* __restrict__ qkv, float* __restrict__ out) {
    extern __shared__ float sm[];
    float* Qt   = sm;                  // [d][i]  64x68
    float* Kt   = Qt + 64 * SMPAD;     // [d][j]
    float* Vs   = Kt + 64 * SMPAD;     // [j][d]
    float* Pt   = Vs + 64 * SMPAD;     // [j][i]
    float* mrow = Pt + 64 * SMPAD;
    float* lrow = mrow + 64;
    float* frow = lrow + 64;

    const int tid = threadIdx.x;
    const int tx  = tid & 15;
    const int ty  = tid >> 4;
    const int b   = blockIdx.z, h = blockIdx.y;
    const int qs  = blockIdx.x * 64;

    const int rr = tid >> 4;
    const int d4 = (tid & 15) << 2;

    const float* Qb = qkv + (size_t)(b * SEQ + qs) * QKV_LD + h * D_HEAD;
    #pragma unroll
    for (int p = 0; p < 4; p++) {
        int i = rr + p * 16;
        float4 v = *(const float4*)(Qb + (size_t)i * QKV_LD + d4);
        Qt[(d4 + 0) * SMPAD + i] = v.x;
        Qt[(d4 + 1) * SMPAD + i] = v.y;
        Qt[(d4 + 2) * SMPAD + i] = v.z;
        Qt[(d4 + 3) * SMPAD + i] = v.w;
    }
    if (tid < 64) { mrow[tid] = -CUDART_INF_F; lrow[tid] = 0.f; }

    float o[4][4];
    #pragma unroll
    for (int r = 0; r < 4; r++)
        #pragma unroll
        for (int c = 0; c < 4; c++) o[r][c] = 0.f;

    const float* Kbase = qkv + (size_t)(b * SEQ) * QKV_LD + D_MODEL + h * D_HEAD;
    const float* Vbase = Kbase + D_MODEL;

    for (int ch = 0; ch < 5; ch++) {
        __syncthreads();
        const int j0 = qs + ch * 64;

        #pragma unroll
        for (int p = 0; p < 4; p++) {
            int jj = rr + p * 16;
            int jr = min(j0 + jj, SEQ - 1);
            float4 kv = *(const float4*)(Kbase + (size_t)jr * QKV_LD + d4);
            Kt[(d4 + 0) * SMPAD + jj] = kv.x;
            Kt[(d4 + 1) * SMPAD + jj] = kv.y;
            Kt[(d4 + 2) * SMPAD + jj] = kv.z;
            Kt[(d4 + 3) * SMPAD + jj] = kv.w;
            float4 vv = *(const float4*)(Vbase + (size_t)jr * QKV_LD + d4);
            *(float4*)(Vs + jj * SMPAD + d4) = vv;
        }
        __syncthreads();

        float s[4][4];
        #pragma unroll
        for (int r = 0; r < 4; r++)
            #pragma unroll
            for (int c = 0; c < 4; c++) s[r][c] = 0.f;
        #pragma unroll
        for (int d = 0; d < 64; d++) {
            float4 q4 = *(const float4*)(Qt + d * SMPAD + 4 * ty);
            float4 k4 = *(const float4*)(Kt + d * SMPAD + 4 * tx);
            s[0][0] += q4.x * k4.x; s[0][1] += q4.x * k4.y; s[0][2] += q4.x * k4.z; s[0][3] += q4.x * k4.w;
            s[1][0] += q4.y * k4.x; s[1][1] += q4.y * k4.y; s[1][2] += q4.y * k4.z; s[1][3] += q4.y * k4.w;
            s[2][0] += q4.z * k4.x; s[2][1] += q4.z * k4.y; s[2][2] += q4.z * k4.z; s[2][3] += q4.z * k4.w;
            s[3][0] += q4.w * k4.x; s[3][1] += q4.w * k4.y; s[3][2] += q4.w * k4.z; s[3][3] += q4.w * k4.w;
        }
        #pragma unroll
        for (int r = 0; r < 4; r++) {
            #pragma unroll
            for (int c = 0; c < 4; c++) {
                int qi = 4 * ty + r, jl = 4 * tx + c;
                int dj = ch * 64 + jl - qi;
                bool keep = (dj >= 0) && (dj < WINDOW) && (j0 + jl < SEQ);
                Pt[jl * SMPAD + qi] = keep ? s[r][c] * 0.125f : -CUDART_INF_F;
            }
        }
        __syncthreads();

        if (tid < 64) {
            float m = mrow[tid];
            float mc = -CUDART_INF_F;
            #pragma unroll
            for (int jl = 0; jl < 64; jl++) mc = fmaxf(mc, Pt[jl * SMPAD + tid]);
            float mn = fmaxf(m, mc);
            float f  = __expf(m - mn);
            float ssum = 0.f;
            #pragma unroll
            for (int jl = 0; jl < 64; jl++) {
                float p = __expf(Pt[jl * SMPAD + tid] - mn);
                ssum += p;
                Pt[jl * SMPAD + tid] = p;
            }
            lrow[tid] = lrow[tid] * f + ssum;
            mrow[tid] = mn;
            frow[tid] = f;
        }
        __syncthreads();

        float fr0 = frow[4 * ty + 0], fr1 = frow[4 * ty + 1];
        float fr2 = frow[4 * ty + 2], fr3 = frow[4 * ty + 3];
        #pragma unroll
        for (int c = 0; c < 4; c++) {
            o[0][c] *= fr0; o[1][c] *= fr1; o[2][c] *= fr2; o[3][c] *= fr3;
        }
        #pragma unroll
        for (int jl = 0; jl < 64; jl++) {
            float4 p4 = *(const float4*)(Pt + jl * SMPAD + 4 * ty);
            float4 v4 = *(const float4*)(Vs + jl * SMPAD + 4 * tx);
            o[0][0] += p4.x * v4.x; o[0][1] += p4.x * v4.y; o[0][2] += p4.x * v4.z; o[0][3] += p4.x * v4.w;
            o[1][0] += p4.y * v4.x; o[1][1] += p4.y * v4.y; o[1][2] += p4.y * v4.z; o[1][3] += p4.y * v4.w;
            o[2][0] += p4.z * v4.x; o[2][1] += p4.z * v4.y; o[2][2] += p4.z * v4.z; o[2][3] += p4.z * v4.w;
            o[3][0] += p4.w * v4.x; o[3][1] += p4.w * v4.y; o[3][2] += p4.w * v4.z; o[3][3] += p4.w * v4.w;
        }
    }

    #pragma unroll
    for (int r = 0; r < 4; r++) {
        int qi = 4 * ty + r;
        float inv = 1.f / lrow[qi];
        float4 res = make_float4(to_tf32(o[r][0] * inv), to_tf32(o[r][1] * inv),
                                 to_tf32(o[r][2] * inv), to_tf32(o[r][3] * inv));
        *(float4*)(out + (size_t)(b * SEQ + qs + qi) * D_MODEL + h * D_HEAD + 4 * tx) = res;
    }
}

// ---------------------------------------------------------------------------
extern "C" void kernel_launch(void* const* d_in, const int* in_sizes, int n_in,
                              void* d_out, int out_size) {
    const float* x    = (const float*)d_in[0];   // [2,2048,1024]
    const float* Wqkv = (const float*)d_in[1];   // [1024,3072]
    const float* bqkv = (const float*)d_in[2];   // [3072]
    const float* Wout = (const float*)d_in[3];   // [1024,1024]
    const float* bout = (const float*)d_in[4];   // [1024]
    float* out = (float*)d_out;                  // [2,2048,1024] f32

    float *qkv, *att, *xc, *wqkvc, *woutc;
    cudaGetSymbolAddress((void**)&qkv,   g_qkv);
    cudaGetSymbolAddress((void**)&att,   g_att);
    cudaGetSymbolAddress((void**)&xc,    g_xc);
    cudaGetSymbolAddress((void**)&wqkvc, g_wqkvc);
    cudaGetSymbolAddress((void**)&woutc, g_woutc);

    cudaFuncSetAttribute(attn_win, cudaFuncAttributeMaxDynamicSharedMemorySize,
                         ATTN_SMEM);
    cudaFuncSetAttribute(gemm_tf32p, cudaFuncAttributeMaxDynamicSharedMemorySize,
                         GEMM_SMEM);

    // 0) one-shot tf32 rounding of GEMM inputs
    {
        int n4x = M_ROWS * D_MODEL / 4;
        cvt_tf32_vec<<<(n4x + 255) / 256, 256>>>((const float4*)x, (float4*)xc, n4x);
        int n4q = D_MODEL * QKV_LD / 4;
        cvt_tf32_vec<<<(n4q + 255) / 256, 256>>>((const float4*)Wqkv, (float4*)wqkvc, n4q);
        int n4o = D_MODEL * D_MODEL / 4;
        cvt_tf32_vec<<<(n4o + 255) / 256, 256>>>((const float4*)Wout, (float4*)woutc, n4o);
    }

    // 1) QKV projection: [4096,1024] @ [1024,3072] + b
    gemm_tf32p<<<dim3(QKV_LD / 128, M_ROWS / 128), 256, GEMM_SMEM>>>(
        xc, wqkvc, bqkv, qkv, M_ROWS, QKV_LD, D_MODEL);

    // 2) windowed attention (emits tf32-rounded output)
    attn_win<<<dim3(SEQ / 64, N_HEADS, BATCH), 256, ATTN_SMEM>>>(qkv, att);

    // 3) output projection: [4096,1024] @ [1024,1024] + b -> d_out
    gemm_tf32p<<<dim3(D_MODEL / 128, M_ROWS / 128), 256, GEMM_SMEM>>>(
        att, woutc, bout, out, M_ROWS, D_MODEL, D_MODEL);
}

// round 16
// speedup vs baseline: 1.7851x; 1.1524x over previous
#include <cuda_runtime.h>
#include <math_constants.h>

#define D_MODEL 1024
#define N_HEADS 16
#define D_HEAD  64
#define WINDOW  256
#define SEQ     2048
#define BATCH   2
#define M_ROWS  (BATCH * SEQ)   // 4096
#define QKV_LD  (3 * D_MODEL)   // 3072

// Scratch (allocation-free rule: __device__ globals)
__device__ float g_qkv[(size_t)M_ROWS * QKV_LD];     // [4096][3072] fp32
__device__ float g_att[(size_t)M_ROWS * D_MODEL];    // [4096][1024] tf32-rounded
__device__ float g_xc[(size_t)M_ROWS * D_MODEL];     // x, tf32-rounded
__device__ float g_wqkvc[(size_t)D_MODEL * QKV_LD];  // W_qkv, tf32-rounded
__device__ float g_woutc[(size_t)D_MODEL * D_MODEL]; // W_out, tf32-rounded

// ---------------------------------------------------------------------------
// helpers (compute_103-safe PTX only: sm_80-era instructions)
// ---------------------------------------------------------------------------
__device__ __forceinline__ float to_tf32(float x) {
    unsigned u;
    asm("cvt.rna.tf32.f32 %0, %1;" : "=r"(u) : "f"(x));
    return __uint_as_float(u);
}
__device__ __forceinline__ float4 cvt4(float4 v) {
    v.x = to_tf32(v.x); v.y = to_tf32(v.y); v.z = to_tf32(v.z); v.w = to_tf32(v.w);
    return v;
}
__device__ __forceinline__ unsigned smem_u32(const void* p) {
    unsigned r;
    asm("{ .reg .u64 t; cvta.to.shared.u64 t, %1; cvt.u32.u64 %0, t; }"
        : "=r"(r) : "l"(p));
    return r;
}
__device__ __forceinline__ void mma_tf32(float* c,
                                         unsigned a0, unsigned a1, unsigned a2, unsigned a3,
                                         unsigned b0, unsigned b1) {
    asm volatile(
        "mma.sync.aligned.m16n8k8.row.col.f32.tf32.tf32.f32 "
        "{%0,%1,%2,%3}, {%4,%5,%6,%7}, {%8,%9}, {%0,%1,%2,%3};\n"
        : "+f"(c[0]), "+f"(c[1]), "+f"(c[2]), "+f"(c[3])
        : "r"(a0), "r"(a1), "r"(a2), "r"(a3), "r"(b0), "r"(b1));
}
__device__ __forceinline__ void cp16(unsigned dst, const float* src) {
    asm volatile("cp.async.cg.shared.global [%0], [%1], 16;\n" :: "r"(dst), "l"(src));
}
#define CP_COMMIT() asm volatile("cp.async.commit_group;\n" ::: "memory")
#define CP_WAIT(n)  asm volatile("cp.async.wait_group %0;\n" :: "n"(n) : "memory")

// ---------------------------------------------------------------------------
// elementwise tf32 rounding (one-shot; hoists cvt off the GEMM path)
// ---------------------------------------------------------------------------
__global__ void cvt_tf32_vec(const float4* __restrict__ in, float4* __restrict__ out,
                             int n4) {
    int i = blockIdx.x * blockDim.x + threadIdx.x;
    if (i < n4) out[i] = cvt4(in[i]);
}

// ---------------------------------------------------------------------------
// Pipelined tf32 GEMM: C[M,N] = A[M,K] @ B[K,N] + bias[N]   (unchanged, WIN R9)
// ---------------------------------------------------------------------------
#define A_ROW 36
#define B_ROW 136
#define A_BYTES (128 * A_ROW * 4)
#define B_OFF_B A_BYTES
#define B_OFF_F (128 * A_ROW)
#define STAGE_B (A_BYTES + 32 * B_ROW * 4)
#define STAGE_F (STAGE_B / 4)
#define NSTAGE 3
#define GEMM_SMEM (NSTAGE * STAGE_B)

__device__ __forceinline__ void load_chunk(unsigned sbase, int stage,
                                           const float* __restrict__ A,
                                           const float* __restrict__ B,
                                           int bm, int bn, int K, int N, int kb,
                                           int tid) {
    const unsigned sa = sbase + (unsigned)stage * STAGE_B;
    #pragma unroll
    for (int p = 0; p < 4; p++) {
        int idx = tid + p * 256;
        int r = idx >> 3, q = idx & 7;
        cp16(sa + (unsigned)r * (A_ROW * 4) + q * 16,
             A + (size_t)(bm + r) * K + kb + q * 4);
    }
    #pragma unroll
    for (int p = 0; p < 4; p++) {
        int idx = tid + p * 256;
        int r = idx >> 5, q = idx & 31;
        cp16(sa + B_OFF_B + (unsigned)r * (B_ROW * 4) + q * 16,
             B + (size_t)(kb + r) * N + bn + q * 4);
    }
}

__global__ __launch_bounds__(256, 2)
void gemm_tf32p(const float* __restrict__ A, const float* __restrict__ B,
                const float* __restrict__ bias, float* __restrict__ C,
                int M, int N, int K) {
    extern __shared__ float smf[];
    const unsigned sbase = smem_u32(smf);
    const int tid = threadIdx.x, lane = tid & 31, wid = tid >> 5;
    const int g = lane >> 2, tg = lane & 3;
    const int wm = (wid & 3) * 32, wn = (wid >> 2) * 64;
    const int bm = blockIdx.y * 128, bn = blockIdx.x * 128;
    const int NC = K / 32;

    float acc[2][8][4] = {};

    load_chunk(sbase, 0, A, B, bm, bn, K, N, 0, tid);
    CP_COMMIT();
    load_chunk(sbase, 1, A, B, bm, bn, K, N, 32, tid);
    CP_COMMIT();

    int stage = 0;
    for (int c = 0; c < NC; c++) {
        CP_WAIT(1);
        __syncthreads();

        if (c + 2 < NC)
            load_chunk(sbase, (stage + 2) % NSTAGE, A, B, bm, bn, K, N,
                       (c + 2) * 32, tid);
        CP_COMMIT();

        const int sb = stage * STAGE_F;
        #pragma unroll
        for (int ks = 0; ks < 4; ks++) {
            const int k8 = ks * 8;
            unsigned a[2][4];
            #pragma unroll
            for (int mt = 0; mt < 2; mt++) {
                int r = wm + mt * 16 + g;
                a[mt][0] = __float_as_uint(smf[sb + r * A_ROW + k8 + tg]);
                a[mt][1] = __float_as_uint(smf[sb + (r + 8) * A_ROW + k8 + tg]);
                a[mt][2] = __float_as_uint(smf[sb + r * A_ROW + k8 + tg + 4]);
                a[mt][3] = __float_as_uint(smf[sb + (r + 8) * A_ROW + k8 + tg + 4]);
            }
            unsigned b0[8], b1[8];
            #pragma unroll
            for (int nt = 0; nt < 8; nt++) {
                int cc = wn + nt * 8 + g;
                b0[nt] = __float_as_uint(smf[sb + B_OFF_F + (k8 + tg) * B_ROW + cc]);
                b1[nt] = __float_as_uint(smf[sb + B_OFF_F + (k8 + tg + 4) * B_ROW + cc]);
            }
            #pragma unroll
            for (int mt = 0; mt < 2; mt++)
                #pragma unroll
                for (int nt = 0; nt < 8; nt++)
                    mma_tf32(acc[mt][nt], a[mt][0], a[mt][1], a[mt][2], a[mt][3],
                             b0[nt], b1[nt]);
        }
        stage = (stage + 1 == NSTAGE) ? 0 : stage + 1;
    }

    #pragma unroll
    for (int mt = 0; mt < 2; mt++) {
        #pragma unroll
        for (int nt = 0; nt < 8; nt++) {
            int r0 = bm + wm + mt * 16 + g;
            int c0 = bn + wn + nt * 8 + 2 * tg;
            float2 bv = *(const float2*)(bias + c0);
            float2 o0 = make_float2(acc[mt][nt][0] + bv.x, acc[mt][nt][1] + bv.y);
            float2 o1 = make_float2(acc[mt][nt][2] + bv.x, acc[mt][nt][3] + bv.y);
            *(float2*)(C + (size_t)r0 * N + c0)       = o0;
            *(float2*)(C + (size_t)(r0 + 8) * N + c0) = o1;
        }
    }
}

// ---------------------------------------------------------------------------
// Windowed attention via mma.sync tf32. Anti-causal window [i, i+255].
// Block = (b, h, 64 queries), 128 threads = 4 warps, warp = 16 q-rows.
// FIX vs R13: output row now includes the b*SEQ batch offset (the R13 bug).
// ---------------------------------------------------------------------------
#define APAD 72
#define ATTN_SMEM (4 * 64 * APAD * 4)   // Qs,Ks,Vs,Ps = 73728 B
#define NEG_BIG (-1e30f)

__global__ __launch_bounds__(128, 3)
void attn_mma(const float* __restrict__ qkv, float* __restrict__ out) {
    extern __shared__ float sm[];
    float* Qs = sm;                 // [q][d] 64x72
    float* Ks = Qs + 64 * APAD;     // [d][j] 64x72  (B operand of S)
    float* Vs = Ks + 64 * APAD;     // [j][d] 64x72  (B operand of PV)
    float* Ps = Vs + 64 * APAD;     // [q][j] 64x72  (A operand of PV)

    const int tid  = threadIdx.x;
    const int lane = tid & 31, wid = tid >> 5;
    const int g = lane >> 2, tg = lane & 3;
    const int wm = wid * 16;
    const int b = blockIdx.z, h = blockIdx.y;
    const int qs = blockIdx.x * 64;

    const int lr = tid >> 1;            // 0..63  (load row)
    const int lc = (tid & 1) * 32;      // 0/32   (load col base)

    // Q tile [q][d], tf32-rounded
    const float* Qb = qkv + (size_t)(b * SEQ + qs) * QKV_LD + h * D_HEAD;
    #pragma unroll
    for (int p = 0; p < 8; p++) {
        int col = lc + p * 4;
        float4 v = *(const float4*)(Qb + (size_t)lr * QKV_LD + col);
        *(float4*)(Qs + lr * APAD + col) = cvt4(v);
    }

    const float* Kbase = qkv + (size_t)(b * SEQ) * QKV_LD + D_MODEL + h * D_HEAD;
    const float* Vbase = Kbase + D_MODEL;

    float o[8][4] = {};
    float mA = NEG_BIG, mB = NEG_BIG, lA = 0.f, lB = 0.f;
    const int rowA = qs + wm + g;        // sequence-local query row A
    const int rowB = rowA + 8;

    for (int ch = 0; ch < 5; ch++) {
        __syncthreads();                 // prev chunk done with Ks/Vs
        const int j0 = qs + ch * 64;

        // K -> Ks[d][j] (transposed), V -> Vs[j][d]; tf32-rounded, clamped rows
        {
            int jr = min(j0 + lr, SEQ - 1);
            #pragma unroll
            for (int p = 0; p < 8; p++) {
                int d0 = lc + p * 4;
                float4 kv = *(const float4*)(Kbase + (size_t)jr * QKV_LD + d0);
                Ks[(d0 + 0) * APAD + lr] = to_tf32(kv.x);
                Ks[(d0 + 1) * APAD + lr] = to_tf32(kv.y);
                Ks[(d0 + 2) * APAD + lr] = to_tf32(kv.z);
                Ks[(d0 + 3) * APAD + lr] = to_tf32(kv.w);
                float4 vv = *(const float4*)(Vbase + (size_t)jr * QKV_LD + d0);
                *(float4*)(Vs + lr * APAD + d0) = cvt4(vv);
            }
        }
        __syncthreads();

        // S = Q K^T  (warp: 16 q-rows x 64 j-cols)
        float s[8][4] = {};
        #pragma unroll
        for (int ks = 0; ks < 8; ks++) {
            const int k8 = ks * 8;
            unsigned a0 = __float_as_uint(Qs[(wm + g) * APAD + k8 + tg]);
            unsigned a1 = __float_as_uint(Qs[(wm + g + 8) * APAD + k8 + tg]);
            unsigned a2 = __float_as_uint(Qs[(wm + g) * APAD + k8 + tg + 4]);
            unsigned a3 = __float_as_uint(Qs[(wm + g + 8) * APAD + k8 + tg + 4]);
            #pragma unroll
            for (int nt = 0; nt < 8; nt++) {
                unsigned b0 = __float_as_uint(Ks[(k8 + tg) * APAD + nt * 8 + g]);
                unsigned b1 = __float_as_uint(Ks[(k8 + tg + 4) * APAD + nt * 8 + g]);
                mma_tf32(s[nt], a0, a1, a2, a3, b0, b1);
            }
        }

        // mask + scale in regs; C-layout: c0:(rA, j), c1:(rA, j+1), c2/c3: rB
        #pragma unroll
        for (int nt = 0; nt < 8; nt++) {
            int j = j0 + nt * 8 + 2 * tg;
            bool in0 = (j < SEQ);
            bool in1 = (j + 1 < SEQ);
            int djA0 = j - rowA, djB0 = j - rowB;
            s[nt][0] = (in0 && djA0 >= 0 && djA0 < WINDOW) ? s[nt][0] * 0.125f : NEG_BIG;
            s[nt][1] = (in1 && djA0 + 1 >= 0 && djA0 + 1 < WINDOW) ? s[nt][1] * 0.125f : NEG_BIG;
            s[nt][2] = (in0 && djB0 >= 0 && djB0 < WINDOW) ? s[nt][2] * 0.125f : NEG_BIG;
            s[nt][3] = (in1 && djB0 + 1 >= 0 && djB0 + 1 < WINDOW) ? s[nt][3] * 0.125f : NEG_BIG;
        }

        // online softmax: row reductions across the quad (tg) via shfl
        float cA = NEG_BIG, cB = NEG_BIG;
        #pragma unroll
        for (int nt = 0; nt < 8; nt++) {
            cA = fmaxf(cA, fmaxf(s[nt][0], s[nt][1]));
            cB = fmaxf(cB, fmaxf(s[nt][2], s[nt][3]));
        }
        cA = fmaxf(cA, __shfl_xor_sync(0xffffffffu, cA, 1));
        cA = fmaxf(cA, __shfl_xor_sync(0xffffffffu, cA, 2));
        cB = fmaxf(cB, __shfl_xor_sync(0xffffffffu, cB, 1));
        cB = fmaxf(cB, __shfl_xor_sync(0xffffffffu, cB, 2));
        float mAn = fmaxf(mA, cA), mBn = fmaxf(mB, cB);
        float fA = __expf(mA - mAn), fB = __expf(mB - mBn);

        float sumA = 0.f, sumB = 0.f;
        #pragma unroll
        for (int nt = 0; nt < 8; nt++) {
            float p0 = __expf(s[nt][0] - mAn);
            float p1 = __expf(s[nt][1] - mAn);
            float p2 = __expf(s[nt][2] - mBn);
            float p3 = __expf(s[nt][3] - mBn);
            sumA += p0 + p1; sumB += p2 + p3;
            int jc = nt * 8 + 2 * tg;
            *(float2*)(Ps + (wm + g) * APAD + jc)     = make_float2(to_tf32(p0), to_tf32(p1));
            *(float2*)(Ps + (wm + g + 8) * APAD + jc) = make_float2(to_tf32(p2), to_tf32(p3));
        }
        sumA += __shfl_xor_sync(0xffffffffu, sumA, 1);
        sumA += __shfl_xor_sync(0xffffffffu, sumA, 2);
        sumB += __shfl_xor_sync(0xffffffffu, sumB, 1);
        sumB += __shfl_xor_sync(0xffffffffu, sumB, 2);
        lA = lA * fA + sumA; lB = lB * fB + sumB;
        mA = mAn; mB = mBn;

        // rescale O, then O += P V
        #pragma unroll
        for (int nt = 0; nt < 8; nt++) {
            o[nt][0] *= fA; o[nt][1] *= fA; o[nt][2] *= fB; o[nt][3] *= fB;
        }
        __syncwarp();                    // Ps rows are warp-private
        #pragma unroll
        for (int ks = 0; ks < 8; ks++) {
            const int k8 = ks * 8;
            unsigned a0 = __float_as_uint(Ps[(wm + g) * APAD + k8 + tg]);
            unsigned a1 = __float_as_uint(Ps[(wm + g + 8) * APAD + k8 + tg]);
            unsigned a2 = __float_as_uint(Ps[(wm + g) * APAD + k8 + tg + 4]);
            unsigned a3 = __float_as_uint(Ps[(wm + g + 8) * APAD + k8 + tg + 4]);
            #pragma unroll
            for (int nt = 0; nt < 8; nt++) {
                unsigned b0 = __float_as_uint(Vs[(k8 + tg) * APAD + nt * 8 + g]);
                unsigned b1 = __float_as_uint(Vs[(k8 + tg + 4) * APAD + nt * 8 + g]);
                mma_tf32(o[nt], a0, a1, a2, a3, b0, b1);
            }
        }
    }

    // finalize: divide by l, write tf32-rounded [B,S,H*dh]  (FIX: + b*SEQ)
    float invA = 1.f / lA, invB = 1.f / lB;
    float* outA = out + ((size_t)(b * SEQ) + rowA) * D_MODEL + h * D_HEAD;
    float* outB = out + ((size_t)(b * SEQ) + rowB) * D_MODEL + h * D_HEAD;
    #pragma unroll
    for (int nt = 0; nt < 8; nt++) {
        int d0 = nt * 8 + 2 * tg;
        *(float2*)(outA + d0) = make_float2(to_tf32(o[nt][0] * invA),
                                            to_tf32(o[nt][1] * invA));
        *(float2*)(outB + d0) = make_float2(to_tf32(o[nt][2] * invB),
                                            to_tf32(o[nt][3] * invB));
    }
}

// ---------------------------------------------------------------------------
extern "C" void kernel_launch(void* const* d_in, const int* in_sizes, int n_in,
                              void* d_out, int out_size) {
    const float* x    = (const float*)d_in[0];   // [2,2048,1024]
    const float* Wqkv = (const float*)d_in[1];   // [1024,3072]
    const float* bqkv = (const float*)d_in[2];   // [3072]
    const float* Wout = (const float*)d_in[3];   // [1024,1024]
    const float* bout = (const float*)d_in[4];   // [1024]
    float* out = (float*)d_out;                  // [2,2048,1024] f32

    float *qkv, *att, *xc, *wqkvc, *woutc;
    cudaGetSymbolAddress((void**)&qkv,   g_qkv);
    cudaGetSymbolAddress((void**)&att,   g_att);
    cudaGetSymbolAddress((void**)&xc,    g_xc);
    cudaGetSymbolAddress((void**)&wqkvc, g_wqkvc);
    cudaGetSymbolAddress((void**)&woutc, g_woutc);

    cudaFuncSetAttribute(attn_mma, cudaFuncAttributeMaxDynamicSharedMemorySize,
                         ATTN_SMEM);
    cudaFuncSetAttribute(gemm_tf32p, cudaFuncAttributeMaxDynamicSharedMemorySize,
                         GEMM_SMEM);

    // 0) one-shot tf32 rounding of GEMM inputs
    {
        int n4x = M_ROWS * D_MODEL / 4;
        cvt_tf32_vec<<<(n4x + 255) / 256, 256>>>((const float4*)x, (float4*)xc, n4x);
        int n4q = D_MODEL * QKV_LD / 4;
        cvt_tf32_vec<<<(n4q + 255) / 256, 256>>>((const float4*)Wqkv, (float4*)wqkvc, n4q);
        int n4o = D_MODEL * D_MODEL / 4;
        cvt_tf32_vec<<<(n4o + 255) / 256, 256>>>((const float4*)Wout, (float4*)woutc, n4o);
    }

    // 1) QKV projection: [4096,1024] @ [1024,3072] + b
    gemm_tf32p<<<dim3(QKV_LD / 128, M_ROWS / 128), 256, GEMM_SMEM>>>(
        xc, wqkvc, bqkv, qkv, M_ROWS, QKV_LD, D_MODEL);

    // 2) windowed attention (tensor-core, emits tf32-rounded output)
    attn_mma<<<dim3(SEQ / 64, N_HEADS, BATCH), 128, ATTN_SMEM>>>(qkv, att);

    // 3) output projection: [4096,1024] @ [1024,1024] + b -> d_out
    gemm_tf32p<<<dim3(D_MODEL / 128, M_ROWS / 128), 256, GEMM_SMEM>>>(
        att, woutc, bout, out, M_ROWS, D_MODEL, D_MODEL);
}

// round 17
// speedup vs baseline: 1.9445x; 1.0893x over previous
#include <cuda_runtime.h>
#include <math_constants.h>

#define D_MODEL 1024
#define N_HEADS 16
#define D_HEAD  64
#define WINDOW  256
#define SEQ     2048
#define BATCH   2
#define M_ROWS  (BATCH * SEQ)   // 4096
#define QKV_LD  (3 * D_MODEL)   // 3072

// Scratch (allocation-free rule: __device__ globals)
__device__ float g_qkv[(size_t)M_ROWS * QKV_LD];     // [4096][3072] tf32-rounded
__device__ float g_att[(size_t)M_ROWS * D_MODEL];    // [4096][1024] tf32-rounded
__device__ float g_xc[(size_t)M_ROWS * D_MODEL];     // x, tf32-rounded
__device__ float g_wqkvc[(size_t)D_MODEL * QKV_LD];  // W_qkv, tf32-rounded
__device__ float g_woutc[(size_t)D_MODEL * D_MODEL]; // W_out, tf32-rounded

// ---------------------------------------------------------------------------
// helpers (compute_103-safe PTX only: sm_80-era instructions)
// ---------------------------------------------------------------------------
__device__ __forceinline__ float to_tf32(float x) {
    unsigned u;
    asm("cvt.rna.tf32.f32 %0, %1;" : "=r"(u) : "f"(x));
    return __uint_as_float(u);
}
__device__ __forceinline__ float4 cvt4(float4 v) {
    v.x = to_tf32(v.x); v.y = to_tf32(v.y); v.z = to_tf32(v.z); v.w = to_tf32(v.w);
    return v;
}
__device__ __forceinline__ unsigned smem_u32(const void* p) {
    unsigned r;
    asm("{ .reg .u64 t; cvta.to.shared.u64 t, %1; cvt.u32.u64 %0, t; }"
        : "=r"(r) : "l"(p));
    return r;
}
__device__ __forceinline__ void mma_tf32(float* c,
                                         unsigned a0, unsigned a1, unsigned a2, unsigned a3,
                                         unsigned b0, unsigned b1) {
    asm volatile(
        "mma.sync.aligned.m16n8k8.row.col.f32.tf32.tf32.f32 "
        "{%0,%1,%2,%3}, {%4,%5,%6,%7}, {%8,%9}, {%0,%1,%2,%3};\n"
        : "+f"(c[0]), "+f"(c[1]), "+f"(c[2]), "+f"(c[3])
        : "r"(a0), "r"(a1), "r"(a2), "r"(a3), "r"(b0), "r"(b1));
}
__device__ __forceinline__ void cp16(unsigned dst, const float* src) {
    asm volatile("cp.async.cg.shared.global [%0], [%1], 16;\n" :: "r"(dst), "l"(src));
}
#define CP_COMMIT() asm volatile("cp.async.commit_group;\n" ::: "memory")
#define CP_WAIT(n)  asm volatile("cp.async.wait_group %0;\n" :: "n"(n) : "memory")

// ---------------------------------------------------------------------------
// elementwise tf32 rounding (one-shot; hoists cvt off the GEMM path)
// ---------------------------------------------------------------------------
__global__ void cvt_tf32_vec(const float4* __restrict__ in, float4* __restrict__ out,
                             int n4) {
    int i = blockIdx.x * blockDim.x + threadIdx.x;
    if (i < n4) out[i] = cvt4(in[i]);
}

// ---------------------------------------------------------------------------
// Pipelined tf32 GEMM: C[M,N] = A[M,K] @ B[K,N] + bias[N]   (WIN R9)
// roundC != 0 -> output written tf32-rounded (for the QKV projection, so the
// attention kernel can consume Q/K/V without any further conversion).
// ---------------------------------------------------------------------------
#define A_ROW 36
#define B_ROW 136
#define A_BYTES (128 * A_ROW * 4)
#define B_OFF_B A_BYTES
#define B_OFF_F (128 * A_ROW)
#define STAGE_B (A_BYTES + 32 * B_ROW * 4)
#define STAGE_F (STAGE_B / 4)
#define NSTAGE 3
#define GEMM_SMEM (NSTAGE * STAGE_B)

__device__ __forceinline__ void load_chunk(unsigned sbase, int stage,
                                           const float* __restrict__ A,
                                           const float* __restrict__ B,
                                           int bm, int bn, int K, int N, int kb,
                                           int tid) {
    const unsigned sa = sbase + (unsigned)stage * STAGE_B;
    #pragma unroll
    for (int p = 0; p < 4; p++) {
        int idx = tid + p * 256;
        int r = idx >> 3, q = idx & 7;
        cp16(sa + (unsigned)r * (A_ROW * 4) + q * 16,
             A + (size_t)(bm + r) * K + kb + q * 4);
    }
    #pragma unroll
    for (int p = 0; p < 4; p++) {
        int idx = tid + p * 256;
        int r = idx >> 5, q = idx & 31;
        cp16(sa + B_OFF_B + (unsigned)r * (B_ROW * 4) + q * 16,
             B + (size_t)(kb + r) * N + bn + q * 4);
    }
}

__global__ __launch_bounds__(256, 2)
void gemm_tf32p(const float* __restrict__ A, const float* __restrict__ B,
                const float* __restrict__ bias, float* __restrict__ C,
                int M, int N, int K, int roundC) {
    extern __shared__ float smf[];
    const unsigned sbase = smem_u32(smf);
    const int tid = threadIdx.x, lane = tid & 31, wid = tid >> 5;
    const int g = lane >> 2, tg = lane & 3;
    const int wm = (wid & 3) * 32, wn = (wid >> 2) * 64;
    const int bm = blockIdx.y * 128, bn = blockIdx.x * 128;
    const int NC = K / 32;

    float acc[2][8][4] = {};

    load_chunk(sbase, 0, A, B, bm, bn, K, N, 0, tid);
    CP_COMMIT();
    load_chunk(sbase, 1, A, B, bm, bn, K, N, 32, tid);
    CP_COMMIT();

    int stage = 0;
    for (int c = 0; c < NC; c++) {
        CP_WAIT(1);
        __syncthreads();

        if (c + 2 < NC)
            load_chunk(sbase, (stage + 2) % NSTAGE, A, B, bm, bn, K, N,
                       (c + 2) * 32, tid);
        CP_COMMIT();

        const int sb = stage * STAGE_F;
        #pragma unroll
        for (int ks = 0; ks < 4; ks++) {
            const int k8 = ks * 8;
            unsigned a[2][4];
            #pragma unroll
            for (int mt = 0; mt < 2; mt++) {
                int r = wm + mt * 16 + g;
                a[mt][0] = __float_as_uint(smf[sb + r * A_ROW + k8 + tg]);
                a[mt][1] = __float_as_uint(smf[sb + (r + 8) * A_ROW + k8 + tg]);
                a[mt][2] = __float_as_uint(smf[sb + r * A_ROW + k8 + tg + 4]);
                a[mt][3] = __float_as_uint(smf[sb + (r + 8) * A_ROW + k8 + tg + 4]);
            }
            unsigned b0[8], b1[8];
            #pragma unroll
            for (int nt = 0; nt < 8; nt++) {
                int cc = wn + nt * 8 + g;
                b0[nt] = __float_as_uint(smf[sb + B_OFF_F + (k8 + tg) * B_ROW + cc]);
                b1[nt] = __float_as_uint(smf[sb + B_OFF_F + (k8 + tg + 4) * B_ROW + cc]);
            }
            #pragma unroll
            for (int mt = 0; mt < 2; mt++)
                #pragma unroll
                for (int nt = 0; nt < 8; nt++)
                    mma_tf32(acc[mt][nt], a[mt][0], a[mt][1], a[mt][2], a[mt][3],
                             b0[nt], b1[nt]);
        }
        stage = (stage + 1 == NSTAGE) ? 0 : stage + 1;
    }

    #pragma unroll
    for (int mt = 0; mt < 2; mt++) {
        #pragma unroll
        for (int nt = 0; nt < 8; nt++) {
            int r0 = bm + wm + mt * 16 + g;
            int c0 = bn + wn + nt * 8 + 2 * tg;
            float2 bv = *(const float2*)(bias + c0);
            float2 o0 = make_float2(acc[mt][nt][0] + bv.x, acc[mt][nt][1] + bv.y);
            float2 o1 = make_float2(acc[mt][nt][2] + bv.x, acc[mt][nt][3] + bv.y);
            if (roundC) {
                o0.x = to_tf32(o0.x); o0.y = to_tf32(o0.y);
                o1.x = to_tf32(o1.x); o1.y = to_tf32(o1.y);
            }
            *(float2*)(C + (size_t)r0 * N + c0)       = o0;
            *(float2*)(C + (size_t)(r0 + 8) * N + c0) = o1;
        }
    }
}

// ---------------------------------------------------------------------------
// Windowed attention via mma.sync tf32. Anti-causal window [i, i+255].
// Block = (b, h, 64 queries), 128 threads = 4 warps, warp = 16 q-rows.
// v2: Q/K/V arrive tf32-pre-rounded from the QKV GEMM. K/V tiles stream in
// natural [j][d] layout via 2-stage cp.async; Q fragments live in registers;
// Qs smem region is reused as Ps. Mixed pads keep all LDS conflict-free:
//   K pad 68 (bank = 4g+tg), V/Q/P pad 72 (bank = 8tg+8nt+g / 8g+tg).
// ---------------------------------------------------------------------------
#define QPAD 72
#define KPAD 68
#define VPAD 72
#define PS_OFF 0
#define KV_OFF (64 * QPAD)                  // 4608 floats
#define KSTG_F (64 * KPAD)                  // 4352
#define VSTG_F (64 * VPAD)                  // 4608
#define KVSTG_F (KSTG_F + VSTG_F)           // 8960
#define ATTN_SMEM ((64 * QPAD + 2 * KVSTG_F) * 4)   // 90112 B
#define NEG_BIG (-1e30f)

__device__ __forceinline__ void attn_load_kv(unsigned sbase, int stage,
                                             const float* __restrict__ Kbase,
                                             const float* __restrict__ Vbase,
                                             int j0, int tid) {
    const int r  = tid >> 1;             // 0..63 key row
    const int c0 = (tid & 1) * 32;       // 0/32 col base
    const int jr = min(j0 + r, SEQ - 1); // clamp; OOB masked later
    const float* ks = Kbase + (size_t)jr * QKV_LD + c0;
    const float* vs = Vbase + (size_t)jr * QKV_LD + c0;
    const unsigned kd = sbase + (unsigned)(KV_OFF + stage * KVSTG_F + r * KPAD + c0) * 4;
    const unsigned vd = sbase + (unsigned)(KV_OFF + stage * KVSTG_F + KSTG_F + r * VPAD + c0) * 4;
    #pragma unroll
    for (int p = 0; p < 8; p++) {
        cp16(kd + p * 16, ks + p * 4);
        cp16(vd + p * 16, vs + p * 4);
    }
}

__global__ __launch_bounds__(128, 2)
void attn_mma(const float* __restrict__ qkv, float* __restrict__ out) {
    extern __shared__ float sm[];
    const unsigned sbase = smem_u32(sm);
    const int tid  = threadIdx.x;
    const int lane = tid & 31, wid = tid >> 5;
    const int g = lane >> 2, tg = lane & 3;
    const int wm = wid * 16;
    const int b = blockIdx.z, h = blockIdx.y;
    const int qs = blockIdx.x * 64;

    const float* Qb    = qkv + (size_t)(b * SEQ + qs) * QKV_LD + h * D_HEAD;
    const float* Kbase = qkv + (size_t)(b * SEQ) * QKV_LD + D_MODEL + h * D_HEAD;
    const float* Vbase = Kbase + D_MODEL;

    // prologue: Q tile (group 1), then KV chunks 0 and 1 (groups 2, 3)
    {
        const int r = tid >> 1, c0 = (tid & 1) * 32;
        const float* qsrc = Qb + (size_t)r * QKV_LD + c0;
        const unsigned qd = sbase + (unsigned)(r * QPAD + c0) * 4;
        #pragma unroll
        for (int p = 0; p < 8; p++) cp16(qd + p * 16, qsrc + p * 4);
        CP_COMMIT();
    }
    attn_load_kv(sbase, 0, Kbase, Vbase, qs, tid);
    CP_COMMIT();
    attn_load_kv(sbase, 1, Kbase, Vbase, qs + 64, tid);
    CP_COMMIT();

    // Q fragments -> registers (loop-invariant A operand of S)
    CP_WAIT(2);
    __syncthreads();
    unsigned qf[8][4];
    #pragma unroll
    for (int ks = 0; ks < 8; ks++) {
        const int k8 = ks * 8;
        qf[ks][0] = __float_as_uint(sm[(wm + g) * QPAD + k8 + tg]);
        qf[ks][1] = __float_as_uint(sm[(wm + g + 8) * QPAD + k8 + tg]);
        qf[ks][2] = __float_as_uint(sm[(wm + g) * QPAD + k8 + tg + 4]);
        qf[ks][3] = __float_as_uint(sm[(wm + g + 8) * QPAD + k8 + tg + 4]);
    }

    float o[8][4] = {};
    float mA = NEG_BIG, mB = NEG_BIG, lA = 0.f, lB = 0.f;
    const int rowA = qs + wm + g;        // sequence-local query row A
    const int rowB = rowA + 8;

    for (int ch = 0; ch < 5; ch++) {
        const int j0 = qs + ch * 64;
        const int stage = ch & 1;
        const int koff = KV_OFF + stage * KVSTG_F;
        const int voff = koff + KSTG_F;

        CP_WAIT(1);                      // chunk ch resident
        __syncthreads();

        // S = Q K^T  (K natural [j][d]; B-frag = K[col][k8+tg])
        float s[8][4] = {};
        #pragma unroll
        for (int ks = 0; ks < 8; ks++) {
            const int k8 = ks * 8;
            #pragma unroll
            for (int nt = 0; nt < 8; nt++) {
                const int col = nt * 8 + g;
                unsigned b0 = __float_as_uint(sm[koff + col * KPAD + k8 + tg]);
                unsigned b1 = __float_as_uint(sm[koff + col * KPAD + k8 + tg + 4]);
                mma_tf32(s[nt], qf[ks][0], qf[ks][1], qf[ks][2], qf[ks][3], b0, b1);
            }
        }

        // mask + scale in regs; C-layout: c0:(rA, j), c1:(rA, j+1), c2/c3: rB
        #pragma unroll
        for (int nt = 0; nt < 8; nt++) {
            int j = j0 + nt * 8 + 2 * tg;
            bool in0 = (j < SEQ);
            bool in1 = (j + 1 < SEQ);
            int djA0 = j - rowA, djB0 = j - rowB;
            s[nt][0] = (in0 && djA0 >= 0 && djA0 < WINDOW) ? s[nt][0] * 0.125f : NEG_BIG;
            s[nt][1] = (in1 && djA0 + 1 >= 0 && djA0 + 1 < WINDOW) ? s[nt][1] * 0.125f : NEG_BIG;
            s[nt][2] = (in0 && djB0 >= 0 && djB0 < WINDOW) ? s[nt][2] * 0.125f : NEG_BIG;
            s[nt][3] = (in1 && djB0 + 1 >= 0 && djB0 + 1 < WINDOW) ? s[nt][3] * 0.125f : NEG_BIG;
        }

        // online softmax: row reductions across the quad (tg) via shfl
        float cA = NEG_BIG, cB = NEG_BIG;
        #pragma unroll
        for (int nt = 0; nt < 8; nt++) {
            cA = fmaxf(cA, fmaxf(s[nt][0], s[nt][1]));
            cB = fmaxf(cB, fmaxf(s[nt][2], s[nt][3]));
        }
        cA = fmaxf(cA, __shfl_xor_sync(0xffffffffu, cA, 1));
        cA = fmaxf(cA, __shfl_xor_sync(0xffffffffu, cA, 2));
        cB = fmaxf(cB, __shfl_xor_sync(0xffffffffu, cB, 1));
        cB = fmaxf(cB, __shfl_xor_sync(0xffffffffu, cB, 2));
        float mAn = fmaxf(mA, cA), mBn = fmaxf(mB, cB);
        float fA = __expf(mA - mAn), fB = __expf(mB - mBn);

        float sumA = 0.f, sumB = 0.f;
        #pragma unroll
        for (int nt = 0; nt < 8; nt++) {
            float p0 = __expf(s[nt][0] - mAn);
            float p1 = __expf(s[nt][1] - mAn);
            float p2 = __expf(s[nt][2] - mBn);
            float p3 = __expf(s[nt][3] - mBn);
            sumA += p0 + p1; sumB += p2 + p3;
            int jc = nt * 8 + 2 * tg;
            *(float2*)(sm + PS_OFF + (wm + g) * QPAD + jc)     = make_float2(to_tf32(p0), to_tf32(p1));
            *(float2*)(sm + PS_OFF + (wm + g + 8) * QPAD + jc) = make_float2(to_tf32(p2), to_tf32(p3));
        }
        sumA += __shfl_xor_sync(0xffffffffu, sumA, 1);
        sumA += __shfl_xor_sync(0xffffffffu, sumA, 2);
        sumB += __shfl_xor_sync(0xffffffffu, sumB, 1);
        sumB += __shfl_xor_sync(0xffffffffu, sumB, 2);
        lA = lA * fA + sumA; lB = lB * fB + sumB;
        mA = mAn; mB = mBn;

        // rescale O, then O += P V  (V natural [j][d]; B-frag = V[k8+tg][col])
        #pragma unroll
        for (int nt = 0; nt < 8; nt++) {
            o[nt][0] *= fA; o[nt][1] *= fA; o[nt][2] *= fB; o[nt][3] *= fB;
        }
        __syncwarp();                    // Ps rows are warp-private
        #pragma unroll
        for (int ks = 0; ks < 8; ks++) {
            const int k8 = ks * 8;
            unsigned a0 = __float_as_uint(sm[PS_OFF + (wm + g) * QPAD + k8 + tg]);
            unsigned a1 = __float_as_uint(sm[PS_OFF + (wm + g + 8) * QPAD + k8 + tg]);
            unsigned a2 = __float_as_uint(sm[PS_OFF + (wm + g) * QPAD + k8 + tg + 4]);
            unsigned a3 = __float_as_uint(sm[PS_OFF + (wm + g + 8) * QPAD + k8 + tg + 4]);
            #pragma unroll
            for (int nt = 0; nt < 8; nt++) {
                const int col = nt * 8 + g;
                unsigned b0 = __float_as_uint(sm[voff + (k8 + tg) * VPAD + col]);
                unsigned b1 = __float_as_uint(sm[voff + (k8 + tg + 4) * VPAD + col]);
                mma_tf32(o[nt], a0, a1, a2, a3, b0, b1);
            }
        }

        // all warps done reading stage ch&1 -> refill it with chunk ch+2
        __syncthreads();
        if (ch + 2 < 5)
            attn_load_kv(sbase, stage, Kbase, Vbase, qs + (ch + 2) * 64, tid);
        CP_COMMIT();                     // uniform group counting
    }

    // finalize: divide by l, write tf32-rounded [B,S,H*dh]
    float invA = 1.f / lA, invB = 1.f / lB;
    float* outA = out + ((size_t)(b * SEQ) + rowA) * D_MODEL + h * D_HEAD;
    float* outB = out + ((size_t)(b * SEQ) + rowB) * D_MODEL + h * D_HEAD;
    #pragma unroll
    for (int nt = 0; nt < 8; nt++) {
        int d0 = nt * 8 + 2 * tg;
        *(float2*)(outA + d0) = make_float2(to_tf32(o[nt][0] * invA),
                                            to_tf32(o[nt][1] * invA));
        *(float2*)(outB + d0) = make_float2(to_tf32(o[nt][2] * invB),
                                            to_tf32(o[nt][3] * invB));
    }
}

// ---------------------------------------------------------------------------
extern "C" void kernel_launch(void* const* d_in, const int* in_sizes, int n_in,
                              void* d_out, int out_size) {
    const float* x    = (const float*)d_in[0];   // [2,2048,1024]
    const float* Wqkv = (const float*)d_in[1];   // [1024,3072]
    const float* bqkv = (const float*)d_in[2];   // [3072]
    const float* Wout = (const float*)d_in[3];   // [1024,1024]
    const float* bout = (const float*)d_in[4];   // [1024]
    float* out = (float*)d_out;                  // [2,2048,1024] f32

    float *qkv, *att, *xc, *wqkvc, *woutc;
    cudaGetSymbolAddress((void**)&qkv,   g_qkv);
    cudaGetSymbolAddress((void**)&att,   g_att);
    cudaGetSymbolAddress((void**)&xc,    g_xc);
    cudaGetSymbolAddress((void**)&wqkvc, g_wqkvc);
    cudaGetSymbolAddress((void**)&woutc, g_woutc);

    cudaFuncSetAttribute(attn_mma, cudaFuncAttributeMaxDynamicSharedMemorySize,
                         ATTN_SMEM);
    cudaFuncSetAttribute(gemm_tf32p, cudaFuncAttributeMaxDynamicSharedMemorySize,
                         GEMM_SMEM);

    // 0) one-shot tf32 rounding of GEMM inputs
    {
        int n4x = M_ROWS * D_MODEL / 4;
        cvt_tf32_vec<<<(n4x + 255) / 256, 256>>>((const float4*)x, (float4*)xc, n4x);
        int n4q = D_MODEL * QKV_LD / 4;
        cvt_tf32_vec<<<(n4q + 255) / 256, 256>>>((const float4*)Wqkv, (float4*)wqkvc, n4q);
        int n4o = D_MODEL * D_MODEL / 4;
        cvt_tf32_vec<<<(n4o + 255) / 256, 256>>>((const float4*)Wout, (float4*)woutc, n4o);
    }

    // 1) QKV projection, output tf32-rounded for the attention kernel
    gemm_tf32p<<<dim3(QKV_LD / 128, M_ROWS / 128), 256, GEMM_SMEM>>>(
        xc, wqkvc, bqkv, qkv, M_ROWS, QKV_LD, D_MODEL, 1);

    // 2) windowed attention (tensor-core, cp.async K/V streaming)
    attn_mma<<<dim3(SEQ / 64, N_HEADS, BATCH), 128, ATTN_SMEM>>>(qkv, att);

    // 3) output projection: [4096,1024] @ [1024,1024] + b -> d_out
    gemm_tf32p<<<dim3(D_MODEL / 128, M_ROWS / 128), 256, GEMM_SMEM>>>(
        att, woutc, bout, out, M_ROWS, D_MODEL, D_MODEL, 0);
}